// round 5
// baseline (speedup 1.0000x reference)
#include <cuda_runtime.h>
#include <math.h>

// ---------------------------------------------------------------------------
// WavetableSynth: B=16, L=48000, W=64, LWT=512
// Hypothesis: ref cumsum = XLA ReduceWindowRewriter(base=16), CPU pipeline:
//   reshape [3000,16]; inner = sequential fold per 16-row (init 0)
//   row sums scanned recursively: 3000 -> (pad 3008) 188 -> (pad 192) 12 -> direct
//   unwind: S_level[m] = inner[m] + ExclRowOffset[row(m)]   (ONE f32 add/level)
// ---------------------------------------------------------------------------

#define BATCH 16
#define LEN   48000
#define NW    64
#define LWT   512
#define BL    (BATCH * LEN)          // 768000

#define INCF  0.032f                 // f32(512/16000)

#define NR0   3000                   // LEN/16
#define NR1   188                    // ceil(3000/16)
#define NR2   12                     // ceil(188/16)

__device__ float g_sums0[BATCH][NR0];   // level-0 row sums
__device__ float g_E1[BATCH][NR0];      // exclusive offsets for level-0 rows
__device__ float g_index[BL];           // final index per element

// ---------------------------------------------------------------------------
// K1: per-16-row sequential folds of increments -> row sums
// ---------------------------------------------------------------------------
__global__ __launch_bounds__(256, 4)
void k1_rowsums(const float* __restrict__ pitch)
{
    int t = blockIdx.x * blockDim.x + threadIdx.x;
    if (t >= BATCH * NR0) return;
    int b = t / NR0;
    int r = t - b * NR0;
    const float4* __restrict__ p4 =
        (const float4*)(pitch + b * LEN + r * 16);

    float acc = 0.0f;
#pragma unroll
    for (int q = 0; q < 4; q++) {
        float4 v = p4[q];
        acc = __fadd_rn(acc, __fmul_rn(INCF, v.x));
        acc = __fadd_rn(acc, __fmul_rn(INCF, v.y));
        acc = __fadd_rn(acc, __fmul_rn(INCF, v.z));
        acc = __fadd_rn(acc, __fmul_rn(INCF, v.w));
    }
    g_sums0[b][r] = acc;
}

// ---------------------------------------------------------------------------
// K2: per-batch level pyramid over the 3000 row sums (one block per batch)
// ---------------------------------------------------------------------------
__global__ __launch_bounds__(256, 1)
void k2_pyramid()
{
    __shared__ float s0[NR0];          // level-1 input (row sums)
    __shared__ float in1[NR1 * 16];    // level-1 inner prefixes (3008)
    __shared__ float in2[NR2 * 16];    // level-2 inner prefixes (192)
    __shared__ float S3[NR2];          // level-3 inclusive scan (12)
    __shared__ float S2[NR1];          // level-2 inclusive values (188)

    const int b = blockIdx.x;
    const int t = threadIdx.x;

    for (int i = t; i < NR0; i += 256) s0[i] = g_sums0[b][i];
    __syncthreads();

    // level-1 inner folds: 188 rows of 16 (pad zeros beyond 3000)
    if (t < NR1) {
        float acc = 0.0f;
        for (int k = 0; k < 16; k++) {
            int idx = t * 16 + k;
            float v = (idx < NR0) ? s0[idx] : 0.0f;
            acc = __fadd_rn(acc, v);
            in1[t * 16 + k] = acc;
        }
    }
    __syncthreads();

    // level-2 inner folds: 12 rows of 16 over the 188 level-1 sums (pad zeros)
    if (t < NR2) {
        float acc = 0.0f;
        for (int k = 0; k < 16; k++) {
            int m = t * 16 + k;
            float v = (m < NR1) ? in1[m * 16 + 15] : 0.0f;
            acc = __fadd_rn(acc, v);
            in2[t * 16 + k] = acc;
        }
    }
    __syncthreads();

    // level-3 direct sequential scan of the 12 level-2 sums
    if (t == 0) {
        float run = 0.0f;
        for (int r = 0; r < NR2; r++) {
            run = __fadd_rn(run, in2[r * 16 + 15]);
            S3[r] = run;
        }
    }
    __syncthreads();

    // level-2 inclusive values: S2[m] = in2[m] + E3[m>>4]
    if (t < NR1) {
        int q = t >> 4;
        float e3 = (q == 0) ? 0.0f : S3[q - 1];
        S2[t] = __fadd_rn(in2[t], e3);
    }
    __syncthreads();

    // level-1 exclusive offsets for level-0 rows:
    // E1[r] = S1[r-1],  S1[m] = in1[m] + E2[m>>4],  E2[q] = S2[q-1]
    for (int r = t; r < NR0; r += 256) {
        float e1;
        if (r == 0) {
            e1 = 0.0f;
        } else {
            int m = r - 1;
            int q = m >> 4;
            float e2 = (q == 0) ? 0.0f : S2[q - 1];
            e1 = __fadd_rn(in1[m], e2);
        }
        g_E1[b][r] = e1;
    }
}

// ---------------------------------------------------------------------------
// K3: emit final index. One thread per level-0 row (16 elements each).
//   S0 = inner0_prefix + E1[row];  x = S0 - inc0;  remainder 512;  snap
// ---------------------------------------------------------------------------
__global__ __launch_bounds__(128, 8)
void k3_index(const float* __restrict__ pitch)
{
    int t = blockIdx.x * blockDim.x + threadIdx.x;
    if (t >= BATCH * NR0) return;
    int b = t / NR0;
    int r = t - b * NR0;

    const float4* __restrict__ pb = (const float4*)(pitch + b * LEN + r * 16);
    const float4* __restrict__ p0 = (const float4*)(pitch + r * 16);
    float4* __restrict__ o4 = (float4*)(g_index + b * LEN + r * 16);

    const float e1 = g_E1[b][r];
    float acc = 0.0f;
#pragma unroll
    for (int q = 0; q < 4; q++) {
        float4 v = pb[q];
        float4 z = p0[q];
        float out[4];
        float vv[4] = {v.x, v.y, v.z, v.w};
        float zz[4] = {z.x, z.y, z.z, z.w};
#pragma unroll
        for (int k = 0; k < 4; k++) {
            acc = __fadd_rn(acc, __fmul_rn(INCF, vv[k]));
            float S0 = __fadd_rn(acc, e1);
            float x  = __fsub_rn(S0, __fmul_rn(INCF, zz[k]));
            float rr = fmodf(x, 512.0f);
            if (rr < 0.0f) rr = __fadd_rn(rr, 512.0f);
            if (__fsub_rn(512.0f, rr) < 1e-5f) rr = 0.0f;
            out[k] = rr;
        }
        o4[q] = make_float4(out[0], out[1], out[2], out[3]);
    }
}

// ---------------------------------------------------------------------------
// K4: synth. Warp per element; lane i handles w=2i,2i+1.
// Wavetable transposed [512][64] in SMEM (conflict-free lane access).
// ---------------------------------------------------------------------------
#define SYNTH_SMEM_BYTES (LWT * NW * 4)   // 131072

__device__ __forceinline__ float synth_one(
    float r, float2 a, const float* __restrict__ wt, int lane)
{
    float fl = floorf(r);
    int   il = (int)fl;
    float al = r - fl;
    int   ih = (int)ceilf(r);
    if (ih >= LWT) ih = 0;
    float2 lo = *(const float2*)(wt + (il << 6) + (lane << 1));
    float2 hi = *(const float2*)(wt + (ih << 6) + (lane << 1));
    float w0 = lo.x + al * (hi.x - lo.x);
    float w1 = lo.y + al * (hi.y - lo.y);
    return w0 * a.x + w1 * a.y;
}

__device__ __forceinline__ float warp_sum(float v)
{
#pragma unroll
    for (int off = 16; off > 0; off >>= 1)
        v += __shfl_xor_sync(0xffffffffu, v, off);
    return v;
}

__global__ __launch_bounds__(1024, 1)
void synth_kernel(const float* __restrict__ env,
                  const float* __restrict__ att,
                  const float* __restrict__ wtab,
                  float* __restrict__ out)
{
    extern __shared__ float wt[];   // [512][64] transposed
    for (int i = threadIdx.x; i < NW * LWT; i += 1024) {
        int w = i >> 9;
        int j = i & (LWT - 1);
        wt[j * NW + w] = wtab[i];
    }
    __syncthreads();

    const int lane = threadIdx.x & 31;
    const int warp = (blockIdx.x << 5) + (threadIdx.x >> 5);
    const int nw   = gridDim.x << 5;
    const float2* __restrict__ att2 = (const float2*)att;

    int e = warp;
    for (; e + 3 * nw < BL; e += 4 * nw) {
        int e0 = e, e1 = e + nw, e2 = e + 2 * nw, e3 = e + 3 * nw;
        float r0 = __ldg(&g_index[e0]);
        float r1 = __ldg(&g_index[e1]);
        float r2 = __ldg(&g_index[e2]);
        float r3 = __ldg(&g_index[e3]);
        float2 a0 = att2[e0 * 32 + lane];
        float2 a1 = att2[e1 * 32 + lane];
        float2 a2 = att2[e2 * 32 + lane];
        float2 a3 = att2[e3 * 32 + lane];
        float ev0 = __ldg(&env[e0]);
        float ev1 = __ldg(&env[e1]);
        float ev2 = __ldg(&env[e2]);
        float ev3 = __ldg(&env[e3]);

        float v0 = warp_sum(synth_one(r0, a0, wt, lane));
        float v1 = warp_sum(synth_one(r1, a1, wt, lane));
        float v2 = warp_sum(synth_one(r2, a2, wt, lane));
        float v3 = warp_sum(synth_one(r3, a3, wt, lane));
        if (lane == 0) {
            out[e0] = v0 * ev0;
            out[e1] = v1 * ev1;
            out[e2] = v2 * ev2;
            out[e3] = v3 * ev3;
        }
    }
    for (; e < BL; e += nw) {
        float r = __ldg(&g_index[e]);
        float2 a = att2[e * 32 + lane];
        float ev = __ldg(&env[e]);
        float v = warp_sum(synth_one(r, a, wt, lane));
        if (lane == 0) out[e] = v * ev;
    }
}

// ---------------------------------------------------------------------------
extern "C" void kernel_launch(void* const* d_in, const int* in_sizes, int n_in,
                              void* d_out, int out_size)
{
    const float* pitch = (const float*)d_in[0];
    const float* env   = (const float*)d_in[1];
    const float* att   = (const float*)d_in[2];
    const float* wtab  = (const float*)d_in[3];
    float* out = (float*)d_out;

    cudaFuncSetAttribute(synth_kernel,
        cudaFuncAttributeMaxDynamicSharedMemorySize, SYNTH_SMEM_BYTES);

    int nsm = 148;
    cudaDeviceGetAttribute(&nsm, cudaDevAttrMultiProcessorCount, 0);

    k1_rowsums<<<(BATCH * NR0 + 255) / 256, 256>>>(pitch);
    k2_pyramid<<<BATCH, 256>>>();
    k3_index<<<(BATCH * NR0 + 127) / 128, 128>>>(pitch);
    synth_kernel<<<nsm, 1024, SYNTH_SMEM_BYTES>>>(env, att, wtab, out);
}